// round 1
// baseline (speedup 1.0000x reference)
#include <cuda_runtime.h>

// Problem constants (fixed by the dataset): u (8,2048,1024) f32, A/B/C/D (1024,1024) f32.
constexpr int N_DIM  = 1024;
constexpr int T_LEN  = 2048;
constexpr int CHUNK  = 64;           // scan chunk length (a^64 underflows -> carries ~0, but exact algo kept)

// Scratch: Bu / X in-place buffer (64 MB) + chunk carries (1 MB). __device__ globals (no allocation).
__device__ float g_Bu[8L * 2048 * 1024];
__device__ float g_carry[8 * (T_LEN / CHUNK) * N_DIM];

// ---------------------------------------------------------------------------
// NT GEMM: out[m,n] = sum_k A[m,k]*B[n,k]  (+ sum_k A2[m,k]*B2[n,k] if DUAL)
// A: [M,K] row-major, B: [N,K] row-major. M%128==0, N%128==0, K%16==0 assumed.
// 128x128 block tile, 8x8 per thread, BK=16, register-prefetch pipeline.
// ---------------------------------------------------------------------------
template <bool DUAL>
__global__ void __launch_bounds__(256, 2)
gemm_nt(const float* __restrict__ A, const float* __restrict__ B,
        const float* __restrict__ A2, const float* __restrict__ B2,
        float* __restrict__ Cout, int M, int N, int K)
{
    constexpr int BM = 128, BN = 128, BK = 16;
    __shared__ float As[BK][BM + 4];
    __shared__ float Bs[BK][BN + 4];

    const int tid  = threadIdx.x;
    const int m0   = blockIdx.y * BM;
    const int n0   = blockIdx.x * BN;

    // load mapping: each thread loads 2 float4 per operand per tile
    const int arow = tid >> 2;            // 0..63 (second load is +64)
    const int acol = (tid & 3) * 4;       // 0,4,8,12 within BK

    // compute mapping
    const int tx = tid & 15;              // n micro-tile
    const int ty = tid >> 4;              // m micro-tile

    float acc[8][8] = {};

    #pragma unroll
    for (int pass = 0; pass < (DUAL ? 2 : 1); ++pass) {
        const float* Ag = (DUAL && pass) ? A2 : A;
        const float* Bg = (DUAL && pass) ? B2 : B;

        const float* Aptr = Ag + (size_t)(m0 + arow) * K + acol;
        const float* Bptr = Bg + (size_t)(n0 + arow) * K + acol;

        float4 a0 = *(const float4*)(Aptr);
        float4 a1 = *(const float4*)(Aptr + (size_t)64 * K);
        float4 b0 = *(const float4*)(Bptr);
        float4 b1 = *(const float4*)(Bptr + (size_t)64 * K);

        for (int k0 = 0; k0 < K; k0 += BK) {
            // regs -> smem (transposed, padded)
            As[acol + 0][arow]      = a0.x;
            As[acol + 1][arow]      = a0.y;
            As[acol + 2][arow]      = a0.z;
            As[acol + 3][arow]      = a0.w;
            As[acol + 0][arow + 64] = a1.x;
            As[acol + 1][arow + 64] = a1.y;
            As[acol + 2][arow + 64] = a1.z;
            As[acol + 3][arow + 64] = a1.w;
            Bs[acol + 0][arow]      = b0.x;
            Bs[acol + 1][arow]      = b0.y;
            Bs[acol + 2][arow]      = b0.z;
            Bs[acol + 3][arow]      = b0.w;
            Bs[acol + 0][arow + 64] = b1.x;
            Bs[acol + 1][arow + 64] = b1.y;
            Bs[acol + 2][arow + 64] = b1.z;
            Bs[acol + 3][arow + 64] = b1.w;
            __syncthreads();

            // prefetch next K tile into regs (overlaps with compute below)
            if (k0 + BK < K) {
                a0 = *(const float4*)(Aptr + k0 + BK);
                a1 = *(const float4*)(Aptr + (size_t)64 * K + k0 + BK);
                b0 = *(const float4*)(Bptr + k0 + BK);
                b1 = *(const float4*)(Bptr + (size_t)64 * K + k0 + BK);
            }

            #pragma unroll
            for (int k = 0; k < BK; ++k) {
                float ra[8], rb[8];
                *(float4*)&ra[0] = *(const float4*)&As[k][ty * 8];
                *(float4*)&ra[4] = *(const float4*)&As[k][ty * 8 + 4];
                *(float4*)&rb[0] = *(const float4*)&Bs[k][tx * 8];
                *(float4*)&rb[4] = *(const float4*)&Bs[k][tx * 8 + 4];
                #pragma unroll
                for (int i = 0; i < 8; ++i)
                    #pragma unroll
                    for (int j = 0; j < 8; ++j)
                        acc[i][j] = fmaf(ra[i], rb[j], acc[i][j]);
            }
            __syncthreads();
        }
    }

    // write out (float4 stores)
    #pragma unroll
    for (int i = 0; i < 8; ++i) {
        const int row = m0 + ty * 8 + i;
        float4 v0 = make_float4(acc[i][0], acc[i][1], acc[i][2], acc[i][3]);
        float4 v1 = make_float4(acc[i][4], acc[i][5], acc[i][6], acc[i][7]);
        *(float4*)&Cout[(size_t)row * N + n0 + tx * 8]     = v0;
        *(float4*)&Cout[(size_t)row * N + n0 + tx * 8 + 4] = v1;
    }
}

// ---------------------------------------------------------------------------
// Chunked parallel scan over T, in-place on g_Bu:  x_t = a * x_{t-1} + Bu_t
// phase1: local scan per (b, chunk, n), store chunk-final into g_carry
// phase2: sequential combine of chunk carries per (b, n)
// phase3: add carried prefix back into each chunk
// ---------------------------------------------------------------------------
__global__ void scan_phase1(const float* __restrict__ Afull, int batch)
{
    const int nChunks = T_LEN / CHUNK;
    int id = blockIdx.x * blockDim.x + threadIdx.x;
    int n  = id & (N_DIM - 1);
    int bc = id >> 10;                 // b*nChunks + c
    if (bc >= batch * nChunks) return;
    int c  = bc % nChunks;
    int b  = bc / nChunks;

    const float a = Afull[(size_t)n * N_DIM + n];   // diag(A)
    size_t base = ((size_t)(b * T_LEN + c * CHUNK)) * N_DIM + n;

    float x = 0.0f;
    #pragma unroll 8
    for (int t = 0; t < CHUNK; ++t) {
        float v = g_Bu[base + (size_t)t * N_DIM];
        x = fmaf(x, a, v);
        g_Bu[base + (size_t)t * N_DIM] = x;
    }
    g_carry[(size_t)bc * N_DIM + n] = x;
}

__global__ void scan_phase2(const float* __restrict__ Afull, int batch)
{
    const int nChunks = T_LEN / CHUNK;
    int id = blockIdx.x * blockDim.x + threadIdx.x;
    if (id >= batch * N_DIM) return;
    int n = id & (N_DIM - 1);
    int b = id >> 10;

    float a  = Afull[(size_t)n * N_DIM + n];
    float aC = a;                      // a^CHUNK via repeated squaring (CHUNK=64=2^6)
    #pragma unroll
    for (int i = 0; i < 6; ++i) aC *= aC;

    float S = 0.0f;                    // true state entering chunk c
    for (int c = 0; c < nChunks; ++c) {
        size_t idx = (size_t)(b * nChunks + c) * N_DIM + n;
        float L = g_carry[idx];        // local chunk-final
        g_carry[idx] = S;              // overwrite with incoming state
        S = fmaf(aC, S, L);
    }
}

__global__ void scan_phase3(const float* __restrict__ Afull, int batch)
{
    const int nChunks = T_LEN / CHUNK;
    int id = blockIdx.x * blockDim.x + threadIdx.x;
    int n  = id & (N_DIM - 1);
    int bc = id >> 10;
    if (bc >= batch * nChunks) return;
    int c  = bc % nChunks;
    int b  = bc / nChunks;

    float S = g_carry[(size_t)bc * N_DIM + n];
    if (S == 0.0f) return;             // chunk 0 and fully-decayed carries skip all traffic

    const float a = Afull[(size_t)n * N_DIM + n];
    size_t base = ((size_t)(b * T_LEN + c * CHUNK)) * N_DIM + n;

    float f = a;                       // x_{t0+t} = L_t + a^{t+1} * S
    #pragma unroll 8
    for (int t = 0; t < CHUNK; ++t) {
        size_t idx = base + (size_t)t * N_DIM;
        g_Bu[idx] = fmaf(f, S, g_Bu[idx]);
        f *= a;
    }
}

// ---------------------------------------------------------------------------
extern "C" void kernel_launch(void* const* d_in, const int* in_sizes, int n_in,
                              void* d_out, int out_size)
{
    const float* u = (const float*)d_in[0];   // (batch, T, m)
    const float* A = (const float*)d_in[1];   // (n, n)
    const float* B = (const float*)d_in[2];   // (n, m)
    const float* C = (const float*)d_in[3];   // (p, n)
    const float* D = (const float*)d_in[4];   // (p, m)
    float* out = (float*)d_out;

    const int M     = in_sizes[0] / N_DIM;    // batch * T = 16384
    const int batch = M / T_LEN;              // 8
    const int nChunks = T_LEN / CHUNK;        // 32

    float* Bu_ptr = nullptr;
    cudaGetSymbolAddress((void**)&Bu_ptr, g_Bu);

    dim3 gemm_grid(N_DIM / 128, M / 128);

    // 1) Bu = u @ B^T
    gemm_nt<false><<<gemm_grid, 256>>>(u, B, nullptr, nullptr, Bu_ptr, M, N_DIM, N_DIM);

    // 2) in-place scan over T
    int p1_threads = batch * nChunks * N_DIM;
    scan_phase1<<<(p1_threads + 255) / 256, 256>>>(A, batch);
    int p2_threads = batch * N_DIM;
    scan_phase2<<<(p2_threads + 255) / 256, 256>>>(A, batch);
    scan_phase3<<<(p1_threads + 255) / 256, 256>>>(A, batch);

    // 3) y = X @ C^T + u @ D^T  (fused dual-K GEMM)
    gemm_nt<true><<<gemm_grid, 256>>>(Bu_ptr, C, u, D, out, M, N_DIM, N_DIM);
}